// round 17
// baseline (speedup 1.0000x reference)
#include <cuda_runtime.h>
#include <cuda_bf16.h>
#include <mma.h>
#include <math.h>
#include <stdint.h>

using namespace nvcuda;

// ---------------- problem constants ----------------
#define T_TOK   4096
#define DM      1024
#define HID     2048
#define NE      8
#define NSLOTS  (T_TOK * 2)

// ---------------- device scratch (zero-init, no runtime allocation) ----------------
__device__ __align__(16) __nv_bfloat16 g_xh[(size_t)T_TOK * DM];
__device__ __align__(16) __nv_bfloat16 g_xl[(size_t)T_TOK * DM];
__device__ __align__(16) __nv_bfloat16 g_w1h[(size_t)NE * DM * HID];
__device__ __align__(16) __nv_bfloat16 g_w1l[(size_t)NE * DM * HID];
__device__ __align__(16) __nv_bfloat16 g_w3h[(size_t)NE * DM * HID];
__device__ __align__(16) __nv_bfloat16 g_w3l[(size_t)NE * DM * HID];
__device__ __align__(16) __nv_bfloat16 g_w2h[(size_t)NE * HID * DM];
__device__ __align__(16) __nv_bfloat16 g_w2l[(size_t)NE * HID * DM];
__device__ __align__(16) __nv_bfloat16 g_s1h[(size_t)DM * HID];
__device__ __align__(16) __nv_bfloat16 g_s1l[(size_t)DM * HID];
__device__ __align__(16) __nv_bfloat16 g_s3h[(size_t)DM * HID];
__device__ __align__(16) __nv_bfloat16 g_s3l[(size_t)DM * HID];
__device__ __align__(16) __nv_bfloat16 g_s2h[(size_t)HID * DM];
__device__ __align__(16) __nv_bfloat16 g_s2l[(size_t)HID * DM];
__device__ __align__(16) __nv_bfloat16 g_acth[(size_t)NSLOTS * HID];
__device__ __align__(16) __nv_bfloat16 g_actl[(size_t)NSLOTS * HID];
__device__ int   g_cnt[NE];
__device__ int   g_off[NE + 1];
__device__ int   g_cursor[NE];
__device__ int   g_top_e[NSLOTS];
__device__ float g_top_g[NSLOTS];
__device__ int   g_perm_tok[NSLOTS];
__device__ float g_perm_gate[NSLOTS];

// ---------------- helpers ----------------
static __device__ __forceinline__ uint32_t moe_smem_u32(const void* p) {
    uint32_t a;
    asm("{ .reg .u64 t; cvta.to.shared.u64 t, %1; cvt.u32.u64 %0, t; }" : "=r"(a) : "l"(p));
    return a;
}
static __device__ __forceinline__ void moe_cp16(uint32_t dst, const void* src) {
    asm volatile("cp.async.cg.shared.global [%0], [%1], 16;" :: "r"(dst), "l"(src));
}
#define MOE_CP_COMMIT() asm volatile("cp.async.commit_group;" ::: "memory")
#define MOE_CP_WAIT0()  asm volatile("cp.async.wait_group 0;" ::: "memory")

// split v = hi + lo (bf16 each)
static __device__ __forceinline__ void moe_split2(float a, float b,
        __nv_bfloat16* __restrict__ hp, __nv_bfloat16* __restrict__ lp) {
    __nv_bfloat162 h = __floats2bfloat162_rn(a, b);
    __nv_bfloat162 l = __floats2bfloat162_rn(a - __bfloat162float(h.x),
                                             b - __bfloat162float(h.y));
    *(__nv_bfloat162*)hp = h;
    *(__nv_bfloat162*)lp = l;
}

// ---------------- routing kernels (verbatim, proven) ----------------
__global__ void moe_zero_counts() { if (threadIdx.x < NE) g_cnt[threadIdx.x] = 0; }

__global__ void moe_router(const float* __restrict__ x, const float* __restrict__ wr) {
    int t = blockIdx.x, tid = threadIdx.x;
    int w = tid >> 5, lane = tid & 31;
    const float* xr = x + (size_t)t * DM;
    float partial = 0.f;
    for (int d = lane; d < DM; d += 32) partial += xr[d] * wr[d * NE + w];
    #pragma unroll
    for (int o = 16; o; o >>= 1) partial += __shfl_xor_sync(0xffffffffu, partial, o);
    __shared__ float logits[NE];
    if (lane == 0) logits[w] = partial;
    __syncthreads();
    if (tid == 0) {
        float mx = logits[0];
        #pragma unroll
        for (int e = 1; e < NE; e++) mx = fmaxf(mx, logits[e]);
        float p[NE];
        #pragma unroll
        for (int e = 0; e < NE; e++) p[e] = expf(logits[e] - mx);
        int e0 = 0;
        #pragma unroll
        for (int e = 1; e < NE; e++) if (p[e] > p[e0]) e0 = e;
        int e1 = (e0 == 0) ? 1 : 0;
        #pragma unroll
        for (int e = 0; e < NE; e++) if (e != e0 && p[e] > p[e1]) e1 = e;
        float s2 = p[e0] + p[e1];
        g_top_e[2*t]   = e0; g_top_g[2*t]   = p[e0] / s2;
        g_top_e[2*t+1] = e1; g_top_g[2*t+1] = p[e1] / s2;
        atomicAdd(&g_cnt[e0], 1);
        atomicAdd(&g_cnt[e1], 1);
    }
}

__global__ void moe_scan() {
    if (threadIdx.x == 0) {
        int acc = 0;
        for (int e = 0; e < NE; e++) { g_off[e] = acc; acc += g_cnt[e]; g_cursor[e] = 0; }
        g_off[NE] = acc;
    }
}

__global__ void moe_scatter() {
    int t = blockIdx.x * blockDim.x + threadIdx.x;
    if (t >= T_TOK) return;
    #pragma unroll
    for (int k = 0; k < 2; k++) {
        int e = g_top_e[2*t + k];
        int pos = g_off[e] + atomicAdd(&g_cursor[e], 1);
        g_perm_tok[pos]  = t;
        g_perm_gate[pos] = g_top_g[2*t + k];
    }
}

// ---------------- pre-pass: fp32 -> bf16 hi/lo split ----------------
__global__ void moe_split_kernel(const float* __restrict__ src,
                                 __nv_bfloat16* __restrict__ h,
                                 __nv_bfloat16* __restrict__ l) {
    size_t i = ((size_t)blockIdx.x * blockDim.x + threadIdx.x) * 4;
    float4 v = *(const float4*)(src + i);
    __nv_bfloat162 h0 = __floats2bfloat162_rn(v.x, v.y);
    __nv_bfloat162 h1 = __floats2bfloat162_rn(v.z, v.w);
    __nv_bfloat162 l0 = __floats2bfloat162_rn(v.x - __bfloat162float(h0.x),
                                              v.y - __bfloat162float(h0.y));
    __nv_bfloat162 l1 = __floats2bfloat162_rn(v.z - __bfloat162float(h1.x),
                                              v.w - __bfloat162float(h1.y));
    uint2 hu, lu;
    hu.x = *(uint32_t*)&h0; hu.y = *(uint32_t*)&h1;
    lu.x = *(uint32_t*)&l0; lu.y = *(uint32_t*)&l1;
    *(uint2*)(h + i) = hu;
    *(uint2*)(l + i) = lu;
}

// ==========================================================================
// GEMM1: act = silu(Xg@W1) * (Xg@W3), split-bf16 wmma, cp.async double-buffer
// Tile 128x64, K-chunk 16, 8 warps (4m x 2n), warp tile 32x32.
// Stage (21504B): Ah[128][24]b16@0  Al@6144  B1h[16][72]@12288  B1l@14592
//                 B3h@16896  B3l@19200.  2 stages = 43008B static smem.
// ==========================================================================
template <bool ROUTED>
__global__ void __launch_bounds__(256, 2) moe_g1(
        const __nv_bfloat16* __restrict__ W1h, const __nv_bfloat16* __restrict__ W1l,
        const __nv_bfloat16* __restrict__ W3h, const __nv_bfloat16* __restrict__ W3l,
        int Mtot) {
    int r0, r1;
    if (ROUTED) {
        int eidx = blockIdx.z; r0 = g_off[eidx]; r1 = g_off[eidx + 1];
        size_t eo = (size_t)eidx * DM * HID;
        W1h += eo; W1l += eo; W3h += eo; W3l += eo;
    } else { r0 = 0; r1 = Mtot; }
    int mBase = r0 + blockIdx.x * 128;
    if (mBase >= r1) return;
    int n0 = blockIdx.y * 64;

    __shared__ __align__(16) char smem[43008];
    uint32_t sb = moe_smem_u32(smem);

    int tid = threadIdx.x, wid = tid >> 5;
    int warpM = (wid & 3) * 32, warpN = (wid >> 2) * 32;

    // A loader: 2 thr/row, one 16B chunk each, per h/l
    int ar = tid >> 1, ac = tid & 1;
    const __nv_bfloat16 *aH, *aL;
    {
        int s = mBase + ar; if (s >= r1) s = r1 - 1;
        int tok = ROUTED ? g_perm_tok[s] : s;
        aH = g_xh + (size_t)tok * DM + ac * 8;
        aL = g_xl + (size_t)tok * DM + ac * 8;
    }
    uint32_t dA = (uint32_t)ar * 48 + ac * 16;

    // B loader: sel over {W1h,W1l,W3h,W3l}, 64 thr each: 16 k-rows x 4 col-quads
    int bsel = tid >> 6, bidx = tid & 63, brow = bidx >> 2, bq = bidx & 3;
    const __nv_bfloat16* bp = (bsel == 0) ? W1h : (bsel == 1) ? W1l
                            : (bsel == 2) ? W3h : W3l;
    const __nv_bfloat16* bB = bp + (size_t)brow * HID + n0 + bq * 16;
    uint32_t dB = 12288u + bsel * 2304 + brow * 144 + bq * 32;

    wmma::fragment<wmma::accumulator, 16, 16, 16, float> c1[2][2], c3[2][2];
    #pragma unroll
    for (int mi = 0; mi < 2; mi++)
        #pragma unroll
        for (int ni = 0; ni < 2; ni++) {
            wmma::fill_fragment(c1[mi][ni], 0.f);
            wmma::fill_fragment(c3[mi][ni], 0.f);
        }

    auto issue = [&](int k, int b) {
        uint32_t bb = sb + b * 21504;
        int k0 = k * 16;
        moe_cp16(bb + dA,        aH + k0);
        moe_cp16(bb + 6144 + dA, aL + k0);
        const __nv_bfloat16* s = bB + (size_t)k0 * HID;
        moe_cp16(bb + dB,      s);
        moe_cp16(bb + dB + 16, s + 8);
    };

    const int Ksteps = DM / 16;   // 64
    issue(0, 0); MOE_CP_COMMIT();
    MOE_CP_WAIT0(); __syncthreads();

    for (int k = 0; k < Ksteps; k++) {
        if (k + 1 < Ksteps) issue(k + 1, (k + 1) & 1);
        MOE_CP_COMMIT();

        const char* bb = smem + (k & 1) * 21504;
        const __nv_bfloat16* Ah  = (const __nv_bfloat16*)(bb);
        const __nv_bfloat16* Al  = (const __nv_bfloat16*)(bb + 6144);
        const __nv_bfloat16* B1h = (const __nv_bfloat16*)(bb + 12288);
        const __nv_bfloat16* B1l = (const __nv_bfloat16*)(bb + 14592);
        const __nv_bfloat16* B3h = (const __nv_bfloat16*)(bb + 16896);
        const __nv_bfloat16* B3l = (const __nv_bfloat16*)(bb + 19200);

        wmma::fragment<wmma::matrix_a, 16, 16, 16, __nv_bfloat16, wmma::row_major> afh[2], afl[2];
        wmma::fragment<wmma::matrix_b, 16, 16, 16, __nv_bfloat16, wmma::row_major> bh[2], bl[2];
        #pragma unroll
        for (int mi = 0; mi < 2; mi++) {
            wmma::load_matrix_sync(afh[mi], Ah + (warpM + mi * 16) * 24, 24);
            wmma::load_matrix_sync(afl[mi], Al + (warpM + mi * 16) * 24, 24);
        }
        #pragma unroll
        for (int ni = 0; ni < 2; ni++) {
            wmma::load_matrix_sync(bh[ni], B1h + warpN + ni * 16, 72);
            wmma::load_matrix_sync(bl[ni], B1l + warpN + ni * 16, 72);
        }
        #pragma unroll
        for (int mi = 0; mi < 2; mi++)
            #pragma unroll
            for (int ni = 0; ni < 2; ni++) {
                wmma::mma_sync(c1[mi][ni], afh[mi], bh[ni], c1[mi][ni]);
                wmma::mma_sync(c1[mi][ni], afh[mi], bl[ni], c1[mi][ni]);
                wmma::mma_sync(c1[mi][ni], afl[mi], bh[ni], c1[mi][ni]);
            }
        #pragma unroll
        for (int ni = 0; ni < 2; ni++) {
            wmma::load_matrix_sync(bh[ni], B3h + warpN + ni * 16, 72);
            wmma::load_matrix_sync(bl[ni], B3l + warpN + ni * 16, 72);
        }
        #pragma unroll
        for (int mi = 0; mi < 2; mi++)
            #pragma unroll
            for (int ni = 0; ni < 2; ni++) {
                wmma::mma_sync(c3[mi][ni], afh[mi], bh[ni], c3[mi][ni]);
                wmma::mma_sync(c3[mi][ni], afh[mi], bl[ni], c3[mi][ni]);
                wmma::mma_sync(c3[mi][ni], afl[mi], bh[ni], c3[mi][ni]);
            }

        MOE_CP_WAIT0(); __syncthreads();
    }

    // epilogue: SwiGLU elementwise on identical-layout accumulators, via smem fp32
    float* Sf = (float*)smem;   // [128][68] = 34816B
    #pragma unroll
    for (int mi = 0; mi < 2; mi++)
        #pragma unroll
        for (int ni = 0; ni < 2; ni++) {
            #pragma unroll
            for (int e = 0; e < c1[mi][ni].num_elements; e++) {
                float h1 = c1[mi][ni].x[e], h3 = c3[mi][ni].x[e];
                c1[mi][ni].x[e] = h1 * h3 / (1.f + __expf(-h1));
            }
            wmma::store_matrix_sync(Sf + (warpM + mi * 16) * 68 + (warpN + ni * 16),
                                    c1[mi][ni], 68, wmma::mem_row_major);
        }
    __syncthreads();

    {
        int row = tid >> 1, cb = (tid & 1) * 32;
        int slot = mBase + row;
        if (slot < r1) {
            const float* s = Sf + row * 68 + cb;
            __nv_bfloat16* dh = g_acth + (size_t)slot * HID + n0 + cb;
            __nv_bfloat16* dl = g_actl + (size_t)slot * HID + n0 + cb;
            #pragma unroll
            for (int j = 0; j < 16; j++)
                moe_split2(s[2*j], s[2*j + 1], dh + 2*j, dl + 2*j);
        }
    }
}

// ==========================================================================
// GEMM2: Y = act @ W2 (+combine). Tile 128x64, K-chunk 16, warp tile 32x32.
// Stage (16896B): Ah@0  Al@6144  Bh[16][72]@12288  Bl@14592.
// 2 stages = 33792B; epilogue fp32 [128][68] = 34816B -> smem 34816.
// ==========================================================================
template <bool ROUTED>
__global__ void __launch_bounds__(256, 2) moe_g2(
        const __nv_bfloat16* __restrict__ W2h, const __nv_bfloat16* __restrict__ W2l,
        float* __restrict__ out, int Mtot) {
    int r0, r1;
    if (ROUTED) {
        int eidx = blockIdx.z; r0 = g_off[eidx]; r1 = g_off[eidx + 1];
        size_t eo = (size_t)eidx * HID * DM;
        W2h += eo; W2l += eo;
    } else { r0 = 0; r1 = Mtot; }
    int mBase = r0 + blockIdx.x * 128;
    if (mBase >= r1) return;
    int n0 = blockIdx.y * 64;

    __shared__ __align__(16) char smem[34816];
    uint32_t sb = moe_smem_u32(smem);

    int tid = threadIdx.x, wid = tid >> 5;
    int warpM = (wid & 3) * 32, warpN = (wid >> 2) * 32;

    int ar = tid >> 1, ac = tid & 1;
    const __nv_bfloat16 *aH, *aL;
    {
        int s = mBase + ar; if (s >= r1) s = r1 - 1;
        aH = g_acth + (size_t)s * HID + ac * 8;
        aL = g_actl + (size_t)s * HID + ac * 8;
    }
    uint32_t dA = (uint32_t)ar * 48 + ac * 16;

    // B loader: 2 arrays (h/l) x 128 thr: 16 k-rows x 8 col chunks
    int bsel = tid >> 7, bidx = tid & 127, brow = bidx >> 3, bq = bidx & 7;
    const __nv_bfloat16* bp = bsel ? W2l : W2h;
    const __nv_bfloat16* bB = bp + (size_t)brow * DM + n0 + bq * 8;
    uint32_t dB = 12288u + bsel * 2304 + brow * 144 + bq * 16;

    wmma::fragment<wmma::accumulator, 16, 16, 16, float> acc[2][2];
    #pragma unroll
    for (int mi = 0; mi < 2; mi++)
        #pragma unroll
        for (int ni = 0; ni < 2; ni++) wmma::fill_fragment(acc[mi][ni], 0.f);

    auto issue = [&](int k, int b) {
        uint32_t bb = sb + b * 16896;
        int k0 = k * 16;
        moe_cp16(bb + dA,        aH + k0);
        moe_cp16(bb + 6144 + dA, aL + k0);
        moe_cp16(bb + dB, bB + (size_t)k0 * DM);
    };

    const int Ksteps = HID / 16;   // 128
    issue(0, 0); MOE_CP_COMMIT();
    MOE_CP_WAIT0(); __syncthreads();

    for (int k = 0; k < Ksteps; k++) {
        if (k + 1 < Ksteps) issue(k + 1, (k + 1) & 1);
        MOE_CP_COMMIT();

        const char* bb = smem + (k & 1) * 16896;
        const __nv_bfloat16* Ah = (const __nv_bfloat16*)(bb);
        const __nv_bfloat16* Al = (const __nv_bfloat16*)(bb + 6144);
        const __nv_bfloat16* Bh = (const __nv_bfloat16*)(bb + 12288);
        const __nv_bfloat16* Bl = (const __nv_bfloat16*)(bb + 14592);

        wmma::fragment<wmma::matrix_a, 16, 16, 16, __nv_bfloat16, wmma::row_major> afh[2], afl[2];
        wmma::fragment<wmma::matrix_b, 16, 16, 16, __nv_bfloat16, wmma::row_major> bfh[2], bfl[2];
        #pragma unroll
        for (int mi = 0; mi < 2; mi++) {
            wmma::load_matrix_sync(afh[mi], Ah + (warpM + mi * 16) * 24, 24);
            wmma::load_matrix_sync(afl[mi], Al + (warpM + mi * 16) * 24, 24);
        }
        #pragma unroll
        for (int ni = 0; ni < 2; ni++) {
            wmma::load_matrix_sync(bfh[ni], Bh + warpN + ni * 16, 72);
            wmma::load_matrix_sync(bfl[ni], Bl + warpN + ni * 16, 72);
        }
        #pragma unroll
        for (int mi = 0; mi < 2; mi++)
            #pragma unroll
            for (int ni = 0; ni < 2; ni++) {
                wmma::mma_sync(acc[mi][ni], afh[mi], bfh[ni], acc[mi][ni]);
                wmma::mma_sync(acc[mi][ni], afh[mi], bfl[ni], acc[mi][ni]);
                wmma::mma_sync(acc[mi][ni], afl[mi], bfh[ni], acc[mi][ni]);
            }

        MOE_CP_WAIT0(); __syncthreads();
    }

    // epilogue through smem fp32
    float* Sf = (float*)smem;   // [128][68]
    #pragma unroll
    for (int mi = 0; mi < 2; mi++)
        #pragma unroll
        for (int ni = 0; ni < 2; ni++)
            wmma::store_matrix_sync(Sf + (warpM + mi * 16) * 68 + (warpN + ni * 16),
                                    acc[mi][ni], 68, wmma::mem_row_major);
    __syncthreads();

    {
        int row = tid >> 1, cb = (tid & 1) * 32;
        int slot = mBase + row;
        if (slot < r1) {
            const float* s = Sf + row * 68 + cb;
            if (ROUTED) {
                int tok = g_perm_tok[slot];
                float g = g_perm_gate[slot];
                float* dst = out + (size_t)tok * DM + n0 + cb;
                #pragma unroll
                for (int j = 0; j < 32; j++) atomicAdd(dst + j, g * s[j]);
            } else {
                float* dst = out + (size_t)slot * DM + n0 + cb;
                #pragma unroll
                for (int j = 0; j < 8; j++)
                    *(float4*)(dst + 4*j) = *(const float4*)(s + 4*j);
            }
        }
    }
}

// ---------------- launch ----------------
// Launch order is chosen so ncu's `-s 5 -c 1` capture window (6th launch)
// lands on moe_g1<false> (the main GEMM), not a routing micro-kernel.
// All reordered launches are data-independent of each other except as noted.
extern "C" void kernel_launch(void* const* d_in, const int* in_sizes, int n_in,
                              void* d_out, int out_size) {
    (void)in_sizes; (void)n_in; (void)out_size;
    const float* x   = (const float*)d_in[0];
    const float* wr  = (const float*)d_in[1];
    const float* w1  = (const float*)d_in[2];
    const float* w3  = (const float*)d_in[3];
    const float* w2  = (const float*)d_in[4];
    const float* sw1 = (const float*)d_in[5];
    const float* sw3 = (const float*)d_in[6];
    const float* sw2 = (const float*)d_in[7];
    float* out = (float*)d_out;

    __nv_bfloat16 *p_xh, *p_xl, *p_w1h, *p_w1l, *p_w3h, *p_w3l, *p_w2h, *p_w2l;
    __nv_bfloat16 *p_s1h, *p_s1l, *p_s3h, *p_s3l, *p_s2h, *p_s2l;
    cudaGetSymbolAddress((void**)&p_xh,  g_xh);
    cudaGetSymbolAddress((void**)&p_xl,  g_xl);
    cudaGetSymbolAddress((void**)&p_w1h, g_w1h);
    cudaGetSymbolAddress((void**)&p_w1l, g_w1l);
    cudaGetSymbolAddress((void**)&p_w3h, g_w3h);
    cudaGetSymbolAddress((void**)&p_w3l, g_w3l);
    cudaGetSymbolAddress((void**)&p_w2h, g_w2h);
    cudaGetSymbolAddress((void**)&p_w2l, g_w2l);
    cudaGetSymbolAddress((void**)&p_s1h, g_s1h);
    cudaGetSymbolAddress((void**)&p_s1l, g_s1l);
    cudaGetSymbolAddress((void**)&p_s3h, g_s3h);
    cudaGetSymbolAddress((void**)&p_s3l, g_s3l);
    cudaGetSymbolAddress((void**)&p_s2h, g_s2h);
    cudaGetSymbolAddress((void**)&p_s2l, g_s2l);

    // launches 0-4: splits needed by the shared-expert GEMM1 + counter zero
    moe_split_kernel<<<(DM * HID) / 1024, 256>>>(sw1, p_s1h, p_s1l);         // 0
    moe_split_kernel<<<(DM * HID) / 1024, 256>>>(sw3, p_s3h, p_s3l);         // 1
    moe_split_kernel<<<(T_TOK * DM) / 1024, 256>>>(x, p_xh, p_xl);           // 2
    moe_split_kernel<<<(HID * DM) / 1024, 256>>>(sw2, p_s2h, p_s2l);         // 3
    moe_zero_counts<<<1, 32>>>();                                            // 4

    // launch 5: main GEMM — ncu capture target
    moe_g1<false><<<dim3(T_TOK / 128, HID / 64, 1), 256>>>(p_s1h, p_s1l, p_s3h, p_s3l, T_TOK); // 5

    // routing chain
    moe_router<<<T_TOK, 256>>>(x, wr);                                       // 6
    moe_scan<<<1, 32>>>();                                                   // 7
    moe_scatter<<<(T_TOK + 255) / 256, 256>>>();                             // 8

    // routed-weight splits
    moe_split_kernel<<<(NE * DM * HID) / 1024, 256>>>(w1, p_w1h, p_w1l);     // 9
    moe_split_kernel<<<(NE * DM * HID) / 1024, 256>>>(w3, p_w3h, p_w3l);     // 10
    moe_split_kernel<<<(NE * HID * DM) / 1024, 256>>>(w2, p_w2h, p_w2l);     // 11

    // shared-expert GEMM2 first (plain stores cover the 0xAA poison in out)
    moe_g2<false><<<dim3(T_TOK / 128, DM / 64, 1), 256>>>(p_s2h, p_s2l, out, T_TOK); // 12

    // routed experts (atomicAdd combine after shared stores)
    moe_g1<true><<<dim3(NSLOTS / 128, HID / 64, NE), 256>>>(p_w1h, p_w1l, p_w3h, p_w3l, 0); // 13
    moe_g2<true><<<dim3(NSLOTS / 128, DM / 64, NE), 256>>>(p_w2h, p_w2l, out, 0);           // 14
}